// round 13
// baseline (speedup 1.0000x reference)
#include <cuda_runtime.h>
#include <cuda_bf16.h>
#include <math.h>
#include <stdint.h>

#define B_    16
#define N_    512
#define IN_   256
#define HID_  128
#define OUT_  256
#define K_    16
#define ROWS_ (B_*N_)   // 8192

typedef __nv_bfloat16 bf16;

// ---------------- scratch (device globals; no runtime allocation) ----------------
__device__ __align__(128) bf16  g_Xh [ROWS_ * IN_],  g_Xl [ROWS_ * IN_];
__device__ __align__(128) bf16  g_W4h[512 * IN_],    g_W4l[512 * IN_];
__device__ __align__(128) bf16  g_WMh[512 * HID_],   g_WMl[512 * HID_];
__device__ __align__(128) float g_B4 [512];
__device__ __align__(128) bf16  g_Qh [ROWS_ * HID_], g_Ql [ROWS_ * HID_];
__device__ __align__(128) bf16  g_Kh [ROWS_ * HID_], g_Kl [ROWS_ * HID_];
__device__ __align__(128) bf16  g_VTh[B_ * HID_ * N_], g_VTl[B_ * HID_ * N_]; // [b][d][m]
__device__ __align__(128) float g_R  [ROWS_ * HID_];
__device__ __align__(128) float g_S  [B_ * N_ * N_];                          // NN scores
__device__ __align__(128) bf16  g_Hh [ROWS_ * HID_], g_Hl [ROWS_ * HID_];
__device__ __align__(128) float g_SQ [ROWS_];
__device__ __align__(128) int   g_IDX[ROWS_ * K_];
__device__ __align__(128) float g_ZG [ROWS_ * 512];

// ---------------- helpers ----------------
__device__ __forceinline__ uint32_t s2u(const void* p) {
    uint32_t a;
    asm("{ .reg .u64 t; cvta.to.shared.u64 t, %1; cvt.u32.u64 %0, t; }" : "=r"(a) : "l"(p));
    return a;
}
__device__ __forceinline__ void ldsm4(uint32_t* r, uint32_t addr) {
    asm volatile("ldmatrix.sync.aligned.m8n8.x4.shared.b16 {%0,%1,%2,%3}, [%4];"
                 : "=r"(r[0]), "=r"(r[1]), "=r"(r[2]), "=r"(r[3]) : "r"(addr));
}
__device__ __forceinline__ void ldsm2(uint32_t* r, uint32_t addr) {
    asm volatile("ldmatrix.sync.aligned.m8n8.x2.shared.b16 {%0,%1}, [%2];"
                 : "=r"(r[0]), "=r"(r[1]) : "r"(addr));
}
__device__ __forceinline__ void mma16816(float* c, const uint32_t* a, const uint32_t* b) {
    asm volatile("mma.sync.aligned.m16n8k16.row.col.f32.bf16.bf16.f32 "
                 "{%0,%1,%2,%3}, {%4,%5,%6,%7}, {%8,%9}, {%0,%1,%2,%3};"
                 : "+f"(c[0]), "+f"(c[1]), "+f"(c[2]), "+f"(c[3])
                 : "r"(a[0]), "r"(a[1]), "r"(a[2]), "r"(a[3]), "r"(b[0]), "r"(b[1]));
}
__device__ __forceinline__ void split2(float x, bf16& h, bf16& l) {
    h = __float2bfloat16_rn(x);
    l = __float2bfloat16_rn(x - __bfloat162float(h));
}
__device__ __forceinline__ void cpa16(uint32_t dst, const void* src) {
    asm volatile("cp.async.cg.shared.global [%0], [%1], 16;" :: "r"(dst), "l"(src));
}
__device__ __forceinline__ void cpa_commit() {
    asm volatile("cp.async.commit_group;" ::: "memory");
}
template <int NN> __device__ __forceinline__ void cpa_wait() {
    asm volatile("cp.async.wait_group %0;" :: "n"(NN) : "memory");
}

// ---------------- input conversion / weight packing (vectorized) ----------------
__global__ void convert_kernel(const float* __restrict__ X,
                               const float* __restrict__ Wq, const float* __restrict__ bq,
                               const float* __restrict__ Wk, const float* __restrict__ bk,
                               const float* __restrict__ Wv, const float* __restrict__ bv,
                               const float* __restrict__ Wr, const float* __restrict__ br,
                               const float* __restrict__ Wc) {
    int t = blockIdx.x * blockDim.x + threadIdx.x;   // 0 .. 524287
    {
        float4 x = *(const float4*)(X + (size_t)t * 4);
        bf16 h0, l0, h1, l1, h2, l2, h3, l3;
        split2(x.x, h0, l0); split2(x.y, h1, l1);
        split2(x.z, h2, l2); split2(x.w, h3, l3);
        __nv_bfloat162 ha; ha.x = h0; ha.y = h1;
        __nv_bfloat162 hb; hb.x = h2; hb.y = h3;
        __nv_bfloat162 la; la.x = l0; la.y = l1;
        __nv_bfloat162 lb; lb.x = l2; lb.y = l3;
        *(__nv_bfloat162*)(g_Xh + (size_t)t * 4)     = ha;
        *(__nv_bfloat162*)(g_Xh + (size_t)t * 4 + 2) = hb;
        *(__nv_bfloat162*)(g_Xl + (size_t)t * 4)     = la;
        *(__nv_bfloat162*)(g_Xl + (size_t)t * 4 + 2) = lb;
    }
    if (t < 512 * IN_) {
        int o = t >> 8, i = t & 255;
        int blk = o >> 7, h = o & 127;
        const float* W = (blk == 0) ? Wq : (blk == 1) ? Wk : (blk == 2) ? Wv : Wr;
        split2(W[i * HID_ + h], g_W4h[t], g_W4l[t]);
    }
    if (t < 512) {
        int blk = t >> 7, h = t & 127;
        const float* sb = (blk == 0) ? bq : (blk == 1) ? bk : (blk == 2) ? bv : br;
        g_B4[t] = sb[h];
    }
    if (t < 512 * HID_) {
        int o = t >> 7, d = t & 127;
        float w2 = Wc[(HID_ + d) * OUT_ + (o & 255)];
        float v  = (o < OUT_) ? w2 : (Wc[d * OUT_ + (o - OUT_)] - w2);
        split2(v, g_WMh[t], g_WMl[t]);
    }
}

// ---------------- shared MMA building blocks ----------------
#define BK      64
#define LDS_    72
#define TILEB_  (128 * LDS_ * 2)
#define TPITCH  132                      // transpose staging pitch (floats, 16B rows)
#define TILEA_  (128 * LDS_ * 2)
#define STAGE_  (2 * TILEA_ + 2 * TILEB_)   // 73728

template <int MI, int NJ>
__device__ __forceinline__ void compute_chunk(
    uint32_t uAh, uint32_t uAl, uint32_t uBh, uint32_t uBl,
    float (&acc)[MI][NJ][4], int lane, int arow0, int brow0) {
    const int arow = arow0 + (lane & 15);
    const int akof = ((lane >> 4) << 3);
    const int brow = brow0 + (lane & 7);
    const int bkof = ((lane >> 3) & 1) << 3;
#pragma unroll
    for (int ks = 0; ks < BK / 16; ks++) {
        const int kk = ks * 16;
        uint32_t aH[MI][4], aL[MI][4], bH[NJ][2], bL[NJ][2];
#pragma unroll
        for (int i = 0; i < MI; i++)
            ldsm4(aH[i], uAh + (uint32_t)(((arow + i * 16) * LDS_ + kk + akof) * 2));
#pragma unroll
        for (int j = 0; j < NJ; j++)
            ldsm2(bH[j], uBh + (uint32_t)(((brow + j * 8) * LDS_ + kk + bkof) * 2));
#pragma unroll
        for (int i = 0; i < MI; i++)
#pragma unroll
            for (int j = 0; j < NJ; j++) mma16816(acc[i][j], aH[i], bH[j]);
#pragma unroll
        for (int i = 0; i < MI; i++)
            ldsm4(aL[i], uAl + (uint32_t)(((arow + i * 16) * LDS_ + kk + akof) * 2));
#pragma unroll
        for (int i = 0; i < MI; i++)
#pragma unroll
            for (int j = 0; j < NJ; j++) mma16816(acc[i][j], aL[i], bH[j]);
#pragma unroll
        for (int j = 0; j < NJ; j++)
            ldsm2(bL[j], uBl + (uint32_t)(((brow + j * 8) * LDS_ + kk + bkof) * 2));
#pragma unroll
        for (int i = 0; i < MI; i++)
#pragma unroll
            for (int j = 0; j < NJ; j++) mma16816(acc[i][j], aH[i], bL[j]);
    }
}

__device__ __forceinline__ void load_tiles_chunk(
    uint32_t ub, const bf16* Ah, const bf16* Al, const bf16* Bh, const bf16* Bl,
    int lda, int ldb, int k0, int tid) {
#pragma unroll
    for (int i = 0; i < 2; i++) {
        int idx = tid + i * 512;
        int r = idx >> 3, c8 = (idx & 7) << 3;
        uint32_t sdst = (uint32_t)((r * LDS_ + c8) * 2);
        cpa16(ub + sdst,          Ah + (size_t)r * lda + k0 + c8);
        cpa16(ub + TILEA_ + sdst, Al + (size_t)r * lda + k0 + c8);
    }
#pragma unroll
    for (int i = 0; i < 2; i++) {
        int idx = tid + i * 512;
        int r = idx >> 3, c8 = (idx & 7) << 3;
        uint32_t sdst = (uint32_t)((r * LDS_ + c8) * 2);
        cpa16(ub + 2 * TILEA_ + sdst,          Bh + (size_t)r * ldb + k0 + c8);
        cpa16(ub + 2 * TILEA_ + TILEB_ + sdst, Bl + (size_t)r * ldb + k0 + c8);
    }
    cpa_commit();
}

// ---------------- QKVR: X @ [Wq|Wk|Wv|Wr] + bias ----------------
__global__ void __launch_bounds__(512, 1) qkvr_kernel() {
    constexpr int nc = IN_ / BK;   // 4
    constexpr int NST = 3;
    extern __shared__ char smem[];
    const int tid = threadIdx.x, lane = tid & 31, w = tid >> 5;
    const int wm = w % 4, wn = w / 4;
    const int nT = blockIdx.x, mT = blockIdx.y;

    const bf16* Ah = g_Xh + (size_t)mT * 128 * IN_;
    const bf16* Al = g_Xl + (size_t)mT * 128 * IN_;
    const bf16* Bh = g_W4h + (size_t)nT * 128 * IN_;
    const bf16* Bl = g_W4l + (size_t)nT * 128 * IN_;

    const uint32_t ubase = s2u(smem);
    float acc[2][4][4] = {};

#pragma unroll
    for (int p = 0; p < NST - 1; p++)
        load_tiles_chunk(ubase + p * STAGE_, Ah, Al, Bh, Bl, IN_, IN_, p * BK, tid);
#pragma unroll
    for (int c = 0; c < nc; c++) {
        if (c + NST - 1 < nc) {
            load_tiles_chunk(ubase + ((c + NST - 1) % NST) * STAGE_, Ah, Al, Bh, Bl,
                             IN_, IN_, (c + NST - 1) * BK, tid);
            cpa_wait<NST - 1>();
        } else if (c + 2 < nc) cpa_wait<2>();
        else if (c + 1 < nc)   cpa_wait<1>();
        else                   cpa_wait<0>();
        __syncthreads();
        const uint32_t ub = ubase + (c % NST) * STAGE_;
        compute_chunk<2, 4>(ub, ub + TILEA_, ub + 2 * TILEA_, ub + 2 * TILEA_ + TILEB_,
                            acc, lane, wm * 32, wn * 32);
        __syncthreads();
    }

    const int r_base = wm * 32 + (lane >> 2);
    const int c_base = wn * 32 + ((lane & 3) << 1);

    if (nT == 2) {   // V -> transposed splits via smem
        float* Cs = (float*)smem;   // [128][129] scalar access
#pragma unroll
        for (int i = 0; i < 2; i++)
#pragma unroll
            for (int j = 0; j < 4; j++) {
                int r = r_base + i * 16, c = c_base + j * 8;
                Cs[r * 129 + c]           = acc[i][j][0] + g_B4[256 + c];
                Cs[r * 129 + c + 1]       = acc[i][j][1] + g_B4[256 + c + 1];
                Cs[(r + 8) * 129 + c]     = acc[i][j][2] + g_B4[256 + c];
                Cs[(r + 8) * 129 + c + 1] = acc[i][j][3] + g_B4[256 + c + 1];
            }
        __syncthreads();
        const int bb = mT >> 2, m0 = (mT & 3) * 128;
        const int d = tid >> 2, ms = (tid & 3) * 32;
        size_t base = ((size_t)bb * HID_ + d) * N_ + m0 + ms;
#pragma unroll 8
        for (int k = 0; k < 32; k++)
            split2(Cs[(ms + k) * 129 + d], g_VTh[base + k], g_VTl[base + k]);
        return;
    }

#pragma unroll
    for (int i = 0; i < 2; i++)
#pragma unroll
        for (int j = 0; j < 4; j++)
#pragma unroll
            for (int h = 0; h < 2; h++) {
                const int r = r_base + i * 16 + h * 8;
                const int c = c_base + j * 8;
                float v0 = acc[i][j][h * 2], v1 = acc[i][j][h * 2 + 1];
                size_t grow = (size_t)mT * 128 + r;
                if (nT == 0 || nT == 1) {
                    bf16* Dh = (nT == 0) ? g_Qh : g_Kh;
                    bf16* Dl = (nT == 0) ? g_Ql : g_Kl;
                    split2(v0 + g_B4[nT * 128 + c],     Dh[grow * HID_ + c],     Dl[grow * HID_ + c]);
                    split2(v1 + g_B4[nT * 128 + c + 1], Dh[grow * HID_ + c + 1], Dl[grow * HID_ + c + 1]);
                } else {
                    *(float2*)(g_R + grow * HID_ + c) =
                        make_float2(v0 + g_B4[384 + c], v1 + g_B4[384 + c + 1]);
                }
            }
}

// ---------------- fused GRAM (scores) + ZG launch ----------------
// jobs 0..159: GRAM upper-tri tiles (b = id/10); jobs 160..415: ZG tiles
__global__ void __launch_bounds__(512, 1) gram_zg_kernel() {
    constexpr int nc = HID_ / BK;   // 2
    extern __shared__ char smem[];
    const int tid = threadIdx.x, lane = tid & 31, w = tid >> 5;
    const int wm = w % 4, wn = w / 4;
    const int id = blockIdx.x;
    const bool gram = id < 160;
    int b = 0, mT, nT;
    if (gram) {
        b = id / 10;
        int t = id % 10;
        mT = (t < 1) ? 0 : (t < 3) ? 1 : (t < 6) ? 2 : 3;
        const int tri[4] = {0, 1, 3, 6};
        nT = t - tri[mT];
    } else {
        int j = id - 160;
        nT = j & 3; mT = j >> 2;
    }

    const bf16 *Ah, *Al, *Bh, *Bl;
    if (gram) {
        size_t ar = ((size_t)b * N_ + mT * 128) * HID_;
        Ah = g_Hh + ar; Al = g_Hl + ar;
        size_t br_ = ((size_t)b * N_ + nT * 128) * HID_;
        Bh = g_Hh + br_; Bl = g_Hl + br_;
    } else {
        size_t ar = (size_t)mT * 128 * HID_;
        Ah = g_Hh + ar; Al = g_Hl + ar;
        size_t br_ = (size_t)nT * 128 * HID_;
        Bh = g_WMh + br_; Bl = g_WMl + br_;
    }

    const uint32_t ubase = s2u(smem);
    float acc[2][4][4] = {};

    load_tiles_chunk(ubase, Ah, Al, Bh, Bl, HID_, HID_, 0, tid);
    load_tiles_chunk(ubase + STAGE_, Ah, Al, Bh, Bl, HID_, HID_, BK, tid);
#pragma unroll
    for (int c = 0; c < nc; c++) {
        if (c + 1 < nc) cpa_wait<1>(); else cpa_wait<0>();
        __syncthreads();
        const uint32_t ub = ubase + c * STAGE_;
        compute_chunk<2, 4>(ub, ub + TILEA_, ub + 2 * TILEA_, ub + 2 * TILEA_ + TILEB_,
                            acc, lane, wm * 32, wn * 32);
        __syncthreads();
    }

    const int r_base = wm * 32 + (lane >> 2);
    const int c_base = wn * 32 + ((lane & 3) << 1);
    float* Ts = (float*)smem;   // transposed staging (stage bufs dead)

#pragma unroll
    for (int i = 0; i < 2; i++)
#pragma unroll
        for (int j = 0; j < 4; j++)
#pragma unroll
            for (int h = 0; h < 2; h++) {
                const int r = r_base + i * 16 + h * 8;
                const int c = c_base + j * 8;
                float v0 = acc[i][j][h * 2], v1 = acc[i][j][h * 2 + 1];
                if (gram) {
                    size_t row = (size_t)b * N_ + mT * 128 + r;
                    float s0 = 2.f * v0 - g_SQ[(size_t)b * N_ + nT * 128 + c];
                    float s1 = 2.f * v1 - g_SQ[(size_t)b * N_ + nT * 128 + c + 1];
                    *(float2*)(g_S + row * N_ + nT * 128 + c) = make_float2(s0, s1);
                    if (mT != nT) {
                        float sqr = g_SQ[(size_t)b * N_ + mT * 128 + r];
                        Ts[c * TPITCH + r]       = 2.f * v0 - sqr;
                        Ts[(c + 1) * TPITCH + r] = 2.f * v1 - sqr;
                    }
                } else {
                    size_t row = (size_t)mT * 128 + r;
                    *(float2*)(g_ZG + row * 512 + nT * 128 + c) = make_float2(v0, v1);
                }
            }

    if (gram && mT != nT) {
        __syncthreads();
        const int c = tid >> 2, ch = (tid & 3) * 32;
        size_t orow = ((size_t)b * N_ + nT * 128 + c) * N_ + mT * 128 + ch;
#pragma unroll
        for (int k = 0; k < 8; k++)
            *(float4*)(g_S + orow + k * 4) = *(const float4*)(Ts + c * TPITCH + ch + k * 4);
    }
}

// ------- fused attention: S = QK^T/sqrt -> softmax -> H = P V + R (+||h||^2) ------
#define QLDS    136
#define Q_TILE  (64 * QLDS * 2)            // 17408
#define KT_TILE (128 * QLDS * 2)           // 34816
#define K_STAGE (2 * KT_TILE)              // 69632
#define ATT_K0  (2 * Q_TILE)               // 34816
#define PLDS    520
#define P_TILE  (64 * PLDS * 2)            // 66560
#define V_OFF   (2 * P_TILE)               // 133120
#define V_HALF  (128 * 72 * 2)             // 18432
#define V_STAGE (2 * V_HALF)               // 36864
#define RED_OFF (V_OFF + 2 * V_STAGE)      // 206848
#define SQ_OFF  (RED_OFF + 2 * 2304)       // 211456
#define SM_ATTN (SQ_OFF + 2048)            // 213504

__global__ void __launch_bounds__(512, 1) attn_kernel() {
    extern __shared__ char smem[];
    const int tid = threadIdx.x, lane = tid & 31, w = tid >> 5;
    const int wm = w & 1, wn = w >> 1;       // 2 M-groups x 8 N-groups
    const int mT = blockIdx.x, b = blockIdx.y;
    const size_t q0 = (size_t)b * N_ + mT * 64;
    const uint32_t ubase = s2u(smem);
    const uint32_t uQh = ubase, uQl = ubase + Q_TILE;

    // ---- phase A: S = Q K^T ----
#pragma unroll
    for (int it = 0; it < 2; it++) {
        int idx = tid + it * 512;
        int r = idx >> 4, c8 = (idx & 15) << 3;
        uint32_t dst = (uint32_t)((r * QLDS + c8) * 2);
        cpa16(uQh + dst, g_Qh + (q0 + r) * HID_ + c8);
        cpa16(uQl + dst, g_Ql + (q0 + r) * HID_ + c8);
    }
    cpa_commit();

    const size_t kr0 = (size_t)b * N_;
    auto loadK = [&](int s, int buf) {
        const uint32_t ub = ubase + ATT_K0 + buf * K_STAGE;
        const bf16* Kh = g_Kh + (kr0 + s * 128) * HID_;
        const bf16* Kl = g_Kl + (kr0 + s * 128) * HID_;
#pragma unroll
        for (int it = 0; it < 4; it++) {
            int idx = tid + it * 512;
            int r = idx >> 4, c8 = (idx & 15) << 3;
            uint32_t dst = (uint32_t)((r * QLDS + c8) * 2);
            cpa16(ub + dst,           Kh + (size_t)r * HID_ + c8);
            cpa16(ub + KT_TILE + dst, Kl + (size_t)r * HID_ + c8);
        }
        cpa_commit();
    };

    float acc[2][8][4] = {};
    loadK(0, 0);
    for (int s = 0; s < 4; s++) {
        if (s + 1 < 4) { loadK(s + 1, (s + 1) & 1); cpa_wait<1>(); }
        else           cpa_wait<0>();
        __syncthreads();
        const uint32_t uKh = ubase + ATT_K0 + (s & 1) * K_STAGE;
        const uint32_t uKl = uKh + KT_TILE;
        const int arow = wm * 32 + (lane & 15);
        const int akof = (lane >> 4) << 3;
        const int brow = wn * 16 + (lane & 7);
        const int bkof = ((lane >> 3) & 1) << 3;
#pragma unroll
        for (int ks = 0; ks < 8; ks++) {
            const int kk = ks * 16;
            uint32_t aH[2][4], aL[2][4], bH[2][2], bL[2][2];
#pragma unroll
            for (int i = 0; i < 2; i++) {
                ldsm4(aH[i], uQh + (uint32_t)(((arow + i * 16) * QLDS + kk + akof) * 2));
                ldsm4(aL[i], uQl + (uint32_t)(((arow + i * 16) * QLDS + kk + akof) * 2));
            }
#pragma unroll
            for (int j = 0; j < 2; j++) {
                uint32_t ba = (uint32_t)(((brow + j * 8) * QLDS + kk + bkof) * 2);
                ldsm2(bH[j], uKh + ba);
                ldsm2(bL[j], uKl + ba);
            }
#pragma unroll
            for (int i = 0; i < 2; i++)
#pragma unroll
                for (int j = 0; j < 2; j++) {
                    mma16816(acc[i][s * 2 + j], aH[i], bH[j]);
                    mma16816(acc[i][s * 2 + j], aL[i], bH[j]);
                    mma16816(acc[i][s * 2 + j], aH[i], bL[j]);
                }
        }
        __syncthreads();
    }

    // prefetch V chunk 0 while softmax runs (region disjoint from red/P)
    auto loadV = [&](int c, int buf) {
        const uint32_t ub = ubase + V_OFF + buf * V_STAGE;
        const bf16* Vh = g_VTh + (size_t)b * HID_ * N_ + c * 64;
        const bf16* Vl = g_VTl + (size_t)b * HID_ * N_ + c * 64;
#pragma unroll
        for (int it = 0; it < 2; it++) {
            int idx = tid + it * 512;
            int r = idx >> 3, c8 = (idx & 7) << 3;
            uint32_t dst = (uint32_t)((r * 72 + c8) * 2);
            cpa16(ub + dst,          Vh + (size_t)r * N_ + c8);
            cpa16(ub + V_HALF + dst, Vl + (size_t)r * N_ + c8);
        }
        cpa_commit();
    };
    loadV(0, 0);

    // ---- softmax over 512 keys (cross-warp via smem) ----
    float* red  = (float*)(smem + RED_OFF);
    float* red2 = (float*)(smem + RED_OFF + 2304);
    const int rq = lane >> 2;
    const float scale = 0.08838834764831843f;
#pragma unroll
    for (int i = 0; i < 2; i++)
#pragma unroll
        for (int nj = 0; nj < 8; nj++)
#pragma unroll
            for (int q = 0; q < 4; q++) acc[i][nj][q] *= scale;

#pragma unroll
    for (int i = 0; i < 2; i++)
#pragma unroll
        for (int h = 0; h < 2; h++) {
            float m = -INFINITY;
#pragma unroll
            for (int nj = 0; nj < 8; nj++)
                m = fmaxf(m, fmaxf(acc[i][nj][h * 2], acc[i][nj][h * 2 + 1]));
            m = fmaxf(m, __shfl_xor_sync(0xffffffffu, m, 1));
            m = fmaxf(m, __shfl_xor_sync(0xffffffffu, m, 2));
            if ((lane & 3) == 0) red[(wm * 32 + i * 16 + h * 8 + rq) * 9 + wn] = m;
        }
    __syncthreads();
    float rm[2][2], ri[2][2];
#pragma unroll
    for (int i = 0; i < 2; i++)
#pragma unroll
        for (int h = 0; h < 2; h++) {
            int row = wm * 32 + i * 16 + h * 8 + rq;
            float m = red[row * 9];
#pragma unroll
            for (int g = 1; g < 8; g++) m = fmaxf(m, red[row * 9 + g]);
            rm[i][h] = m;
        }
#pragma unroll
    for (int i = 0; i < 2; i++)
#pragma unroll
        for (int h = 0; h < 2; h++) {
            float sum = 0.f;
#pragma unroll
            for (int nj = 0; nj < 8; nj++) {
                float e0 = __expf(acc[i][nj][h * 2]     - rm[i][h]);
                float e1 = __expf(acc[i][nj][h * 2 + 1] - rm[i][h]);
                acc[i][nj][h * 2] = e0; acc[i][nj][h * 2 + 1] = e1;
                sum += e0 + e1;
            }
            sum += __shfl_xor_sync(0xffffffffu, sum, 1);
            sum += __shfl_xor_sync(0xffffffffu, sum, 2);
            if ((lane & 3) == 0) red2[(wm * 32 + i * 16 + h * 8 + rq) * 9 + wn] = sum;
        }
    __syncthreads();
#pragma unroll
    for (int i = 0; i < 2; i++)
#pragma unroll
        for (int h = 0; h < 2; h++) {
            int row = wm * 32 + i * 16 + h * 8 + rq;
            float sum = 0.f;
#pragma unroll
            for (int g = 0; g < 8; g++) sum += red2[row * 9 + g];
            ri[i][h] = 1.f / sum;
        }

    // ---- stage P (bf16 h/l) in smem at offset 0 (Q/K regions are dead) ----
    char* pPh = smem;
    char* pPl = smem + P_TILE;
#pragma unroll
    for (int i = 0; i < 2; i++)
#pragma unroll
        for (int nj = 0; nj < 8; nj++)
#pragma unroll
            for (int h = 0; h < 2; h++) {
                int row = wm * 32 + i * 16 + h * 8 + rq;
                int key = (nj >> 1) * 128 + wn * 16 + (nj & 1) * 8 + ((lane & 3) << 1);
                float p0 = acc[i][nj][h * 2] * ri[i][h];
                float p1 = acc[i][nj][h * 2 + 1] * ri[i][h];
                bf16 h0, l0, h1, l1;
                split2(p0, h0, l0); split2(p1, h1, l1);
                __nv_bfloat162 ph; ph.x = h0; ph.y = h1;
                __nv_bfloat162 pl; pl.x = l0; pl.y = l1;
                *(__nv_bfloat162*)(pPh + (row * PLDS + key) * 2) = ph;
                *(__nv_bfloat162*)(pPl + (row * PLDS + key) * 2) = pl;
            }

    // ---- phase C: H = P V (+R), 8 chunks of 64 keys ----
    float acc2[2][2][4] = {};
    const uint32_t uPh = ubase, uPl = ubase + P_TILE;
    for (int c = 0; c < 8; c++) {
        if (c + 1 < 8) { loadV(c + 1, (c + 1) & 1); cpa_wait<1>(); }
        else           cpa_wait<0>();
        __syncthreads();   // also publishes P staging on c==0
        const uint32_t uVh = ubase + V_OFF + (c & 1) * V_STAGE;
        const uint32_t uVl = uVh + V_HALF;
        const int arow = wm * 32 + (lane & 15);
        const int akof = (lane >> 4) << 3;
        const int brow = wn * 16 + (lane & 7);
        const int bkof = ((lane >> 3) & 1) << 3;
#pragma unroll
        for (int ks = 0; ks < 4; ks++) {
            const int pk = c * 64 + ks * 16 + akof;
            const int vk = ks * 16 + bkof;
            uint32_t aH[2][4], aL[2][4], bH[2][2], bL[2][2];
#pragma unroll
            for (int i = 0; i < 2; i++) {
                ldsm4(aH[i], uPh + (uint32_t)(((arow + i * 16) * PLDS + pk) * 2));
                ldsm4(aL[i], uPl + (uint32_t)(((arow + i * 16) * PLDS + pk) * 2));
            }
#pragma unroll
            for (int j = 0; j < 2; j++) {
                uint32_t ba = (uint32_t)(((brow + j * 8) * 72 + vk) * 2);
                ldsm2(bH[j], uVh + ba);
                ldsm2(bL[j], uVl + ba);
            }
#pragma unroll
            for (int i = 0; i < 2; i++)
#pragma unroll
                for (int j = 0; j < 2; j++) {
                    mma16816(acc2[i][j], aH[i], bH[j]);
                    mma16816(acc2[i][j], aL[i], bH[j]);
                    mma16816(acc2[i][j], aH[i], bL[j]);
                }
        }
        __syncthreads();
    }

    // ---- epilogue: H = acc2 + R ; splits ; ||h||^2 ----
    float rsq[2][2] = {{0.f, 0.f}, {0.f, 0.f}};
#pragma unroll
    for (int i = 0; i < 2; i++)
#pragma unroll
        for (int j = 0; j < 2; j++)
#pragma unroll
            for (int h = 0; h < 2; h++) {
                int row = wm * 32 + i * 16 + h * 8 + rq;
                int col = wn * 16 + j * 8 + ((lane & 3) << 1);
                size_t grow = q0 + row;
                float v0 = acc2[i][j][h * 2]     + g_R[grow * HID_ + col];
                float v1 = acc2[i][j][h * 2 + 1] + g_R[grow * HID_ + col + 1];
                split2(v0, g_Hh[grow * HID_ + col],     g_Hl[grow * HID_ + col]);
                split2(v1, g_Hh[grow * HID_ + col + 1], g_Hl[grow * HID_ + col + 1]);
                rsq[i][h] = fmaf(v0, v0, fmaf(v1, v1, rsq[i][h]));
            }
    float* sq_s = (float*)(smem + SQ_OFF);
#pragma unroll
    for (int i = 0; i < 2; i++)
#pragma unroll
        for (int h = 0; h < 2; h++) {
            float v = rsq[i][h];
            v += __shfl_xor_sync(0xffffffffu, v, 1);
            v += __shfl_xor_sync(0xffffffffu, v, 2);
            if ((lane & 3) == 0)
                sq_s[wn * 64 + wm * 32 + i * 16 + h * 8 + rq] = v;
        }
    __syncthreads();
    if (tid < 64) {
        float t = 0.f;
#pragma unroll
        for (int g = 0; g < 8; g++) t += sq_s[g * 64 + tid];
        g_SQ[q0 + tid] = t;
    }
}

// ---------------- top-16 by score (warp per row) ----------------
__global__ __launch_bounds__(256)
void topk_kernel() {
    const int tid = threadIdx.x, lane = tid & 31, w = tid >> 5;
    const int n = blockIdx.x * 8 + w;
    const float* srow = g_S + (size_t)n * N_;
    float cand[16];
#pragma unroll
    for (int s = 0; s < 16; s++) cand[s] = srow[s * 32 + lane];
    const int base = n & ~511;
    unsigned used = 0;
    for (int sel = 0; sel < K_; sel++) {
        float best = -INFINITY;
        int bslot = -1;
#pragma unroll
        for (int s = 0; s < 16; s++)
            if (!((used >> s) & 1u) && cand[s] > best) { best = cand[s]; bslot = s; }
        int   bm = (bslot >= 0) ? ((bslot << 5) | lane) : 0x3fffffff;
        float bv = best;
#pragma unroll
        for (int off = 16; off; off >>= 1) {
            float ov = __shfl_xor_sync(0xffffffffu, bv, off);
            int   om = __shfl_xor_sync(0xffffffffu, bm, off);
            if (ov > bv || (ov == bv && om < bm)) { bv = ov; bm = om; }
        }
        if ((bm & 31) == lane && (bm >> 5) < 16) used |= 1u << (bm >> 5);
        if (lane == 0) g_IDX[(size_t)n * K_ + sel] = base + bm;
    }
}

// ---------------- gather-max + layernorm + selu ----------------
__global__ __launch_bounds__(256)
void final_kernel(const float* __restrict__ bc, const float* __restrict__ lnsc,
                  const float* __restrict__ lnbi, float* __restrict__ out) {
    const int n = blockIdx.x;
    const int o = threadIdx.x;
    const int lane = o & 31, w = o >> 5;
    __shared__ int   sidx[K_];
    __shared__ float red[8];
    __shared__ float sstat;
    if (o < K_) sidx[o] = g_IDX[n * K_ + o];
    __syncthreads();
    float v = -INFINITY;
#pragma unroll
    for (int k = 0; k < K_; k++) v = fmaxf(v, g_ZG[(size_t)sidx[k] * 512 + o]);
    float y = v + g_ZG[(size_t)n * 512 + OUT_ + o] + bc[o];
    float s = y;
#pragma unroll
    for (int off = 16; off; off >>= 1) s += __shfl_xor_sync(0xffffffffu, s, off);
    if (lane == 0) red[w] = s;
    __syncthreads();
    if (o == 0) {
        float t = 0.f;
        for (int i = 0; i < 8; i++) t += red[i];
        sstat = t * (1.f / OUT_);
    }
    __syncthreads();
    const float mu = sstat;
    float d = y - mu;
    s = d * d;
#pragma unroll
    for (int off = 16; off; off >>= 1) s += __shfl_xor_sync(0xffffffffu, s, off);
    if (lane == 0) red[w] = s;
    __syncthreads();
    if (o == 0) {
        float t = 0.f;
        for (int i = 0; i < 8; i++) t += red[i];
        sstat = t * (1.f / OUT_);
    }
    __syncthreads();
    const float var = sstat;
    float nv = d * rsqrtf(var + 1e-5f) * lnsc[o] + lnbi[o];
    float r = nv > 0.f ? 1.0507009873554805f * nv
                       : 1.7580993408473766f * expm1f(nv);
    out[(size_t)n * OUT_ + o] = r;
}

// ---------------- launcher ----------------
extern "C" void kernel_launch(void* const* d_in, const int* in_sizes, int n_in,
                              void* d_out, int out_size) {
    const float* obj = (const float*)d_in[0];
    const float* Wq  = (const float*)d_in[2];
    const float* bq  = (const float*)d_in[3];
    const float* Wk  = (const float*)d_in[4];
    const float* bk  = (const float*)d_in[5];
    const float* Wv  = (const float*)d_in[6];
    const float* bv  = (const float*)d_in[7];
    const float* Wr  = (const float*)d_in[8];
    const float* br  = (const float*)d_in[9];
    const float* Wc  = (const float*)d_in[10];
    const float* bc  = (const float*)d_in[11];
    const float* lns = (const float*)d_in[12];
    const float* lnb = (const float*)d_in[13];
    float* out = (float*)d_out;

    constexpr int SM0  = 3 * STAGE_ + 2048;   // QKVR: nc=4, 3 stages
    constexpr int SM34 = 2 * STAGE_ + 2048;   // GRAM/ZG merged (> 128*132*4 for Ts)

    cudaFuncSetAttribute(qkvr_kernel,    cudaFuncAttributeMaxDynamicSharedMemorySize, SM0);
    cudaFuncSetAttribute(gram_zg_kernel, cudaFuncAttributeMaxDynamicSharedMemorySize, SM34);
    cudaFuncSetAttribute(attn_kernel,    cudaFuncAttributeMaxDynamicSharedMemorySize, SM_ATTN);

    // 1) convert inputs / pack weights (bf16 hi/lo splits), vectorized
    convert_kernel<<<ROWS_ * IN_ / 1024, 256>>>(obj, Wq, bq, Wk, bk, Wv, bv, Wr, br, Wc);
    // 2) QKVR = X @ W4 + bias  ->  Q,K splits; V transposed splits; R fp32
    qkvr_kernel<<<dim3(4, 64, 1), 512, SM0>>>();
    // 3) fused S = QK^T/sqrt + softmax + H = P V + R (+||h||^2)
    attn_kernel<<<dim3(8, B_), 512, SM_ATTN>>>();
    // 4) fused: GRAM scores (160 jobs) + ZG (256 jobs) in one launch
    gram_zg_kernel<<<416, 512, SM34>>>();
    // 5) top-16 neighbors
    topk_kernel<<<ROWS_ / 8, 256>>>();
    // 6) gather-max + LN + selu
    final_kernel<<<ROWS_, 256>>>(bc, lns, lnb, out);
}

// round 14
// speedup vs baseline: 1.6507x; 1.6507x over previous
#include <cuda_runtime.h>
#include <cuda_bf16.h>
#include <math.h>
#include <stdint.h>

#define B_    16
#define N_    512
#define IN_   256
#define HID_  128
#define OUT_  256
#define K_    16
#define ROWS_ (B_*N_)   // 8192

typedef __nv_bfloat16 bf16;

// ---------------- scratch (device globals; no runtime allocation) ----------------
__device__ __align__(128) bf16  g_Xh [ROWS_ * IN_],  g_Xl [ROWS_ * IN_];
__device__ __align__(128) bf16  g_W4h[512 * IN_],    g_W4l[512 * IN_];
__device__ __align__(128) bf16  g_WMh[512 * HID_],   g_WMl[512 * HID_];
__device__ __align__(128) float g_B4 [512];
__device__ __align__(128) bf16  g_Qh [ROWS_ * HID_], g_Ql [ROWS_ * HID_];
__device__ __align__(128) bf16  g_Kh [ROWS_ * HID_], g_Kl [ROWS_ * HID_];
__device__ __align__(128) bf16  g_VTh[B_ * HID_ * N_], g_VTl[B_ * HID_ * N_]; // [b][d][m]
__device__ __align__(128) float g_R  [ROWS_ * HID_];
__device__ __align__(128) float g_S  [B_ * N_ * N_];                          // NN scores
__device__ __align__(128) bf16  g_Hh [ROWS_ * HID_], g_Hl [ROWS_ * HID_];
__device__ __align__(128) float g_SQ [ROWS_];
__device__ __align__(128) int   g_IDX[ROWS_ * K_];
__device__ __align__(128) float g_ZG [ROWS_ * 512];

// ---------------- helpers ----------------
__device__ __forceinline__ uint32_t s2u(const void* p) {
    uint32_t a;
    asm("{ .reg .u64 t; cvta.to.shared.u64 t, %1; cvt.u32.u64 %0, t; }" : "=r"(a) : "l"(p));
    return a;
}
__device__ __forceinline__ void ldsm4(uint32_t* r, uint32_t addr) {
    asm volatile("ldmatrix.sync.aligned.m8n8.x4.shared.b16 {%0,%1,%2,%3}, [%4];"
                 : "=r"(r[0]), "=r"(r[1]), "=r"(r[2]), "=r"(r[3]) : "r"(addr));
}
__device__ __forceinline__ void ldsm2(uint32_t* r, uint32_t addr) {
    asm volatile("ldmatrix.sync.aligned.m8n8.x2.shared.b16 {%0,%1}, [%2];"
                 : "=r"(r[0]), "=r"(r[1]) : "r"(addr));
}
__device__ __forceinline__ void mma16816(float* c, const uint32_t* a, const uint32_t* b) {
    asm volatile("mma.sync.aligned.m16n8k16.row.col.f32.bf16.bf16.f32 "
                 "{%0,%1,%2,%3}, {%4,%5,%6,%7}, {%8,%9}, {%0,%1,%2,%3};"
                 : "+f"(c[0]), "+f"(c[1]), "+f"(c[2]), "+f"(c[3])
                 : "r"(a[0]), "r"(a[1]), "r"(a[2]), "r"(a[3]), "r"(b[0]), "r"(b[1]));
}
__device__ __forceinline__ void split2(float x, bf16& h, bf16& l) {
    h = __float2bfloat16_rn(x);
    l = __float2bfloat16_rn(x - __bfloat162float(h));
}
__device__ __forceinline__ void cpa16(uint32_t dst, const void* src) {
    asm volatile("cp.async.cg.shared.global [%0], [%1], 16;" :: "r"(dst), "l"(src));
}
__device__ __forceinline__ void cpa_commit() {
    asm volatile("cp.async.commit_group;" ::: "memory");
}
template <int NN> __device__ __forceinline__ void cpa_wait() {
    asm volatile("cp.async.wait_group %0;" :: "n"(NN) : "memory");
}

// ---------------- input conversion / weight packing (vectorized) ----------------
__global__ void convert_kernel(const float* __restrict__ X,
                               const float* __restrict__ Wq, const float* __restrict__ bq,
                               const float* __restrict__ Wk, const float* __restrict__ bk,
                               const float* __restrict__ Wv, const float* __restrict__ bv,
                               const float* __restrict__ Wr, const float* __restrict__ br,
                               const float* __restrict__ Wc) {
    int t = blockIdx.x * blockDim.x + threadIdx.x;   // 0 .. 524287
    {
        float4 x = *(const float4*)(X + (size_t)t * 4);
        bf16 h0, l0, h1, l1, h2, l2, h3, l3;
        split2(x.x, h0, l0); split2(x.y, h1, l1);
        split2(x.z, h2, l2); split2(x.w, h3, l3);
        __nv_bfloat162 ha; ha.x = h0; ha.y = h1;
        __nv_bfloat162 hb; hb.x = h2; hb.y = h3;
        __nv_bfloat162 la; la.x = l0; la.y = l1;
        __nv_bfloat162 lb; lb.x = l2; lb.y = l3;
        *(__nv_bfloat162*)(g_Xh + (size_t)t * 4)     = ha;
        *(__nv_bfloat162*)(g_Xh + (size_t)t * 4 + 2) = hb;
        *(__nv_bfloat162*)(g_Xl + (size_t)t * 4)     = la;
        *(__nv_bfloat162*)(g_Xl + (size_t)t * 4 + 2) = lb;
    }
    if (t < 512 * IN_) {
        int o = t >> 8, i = t & 255;
        int blk = o >> 7, h = o & 127;
        const float* W = (blk == 0) ? Wq : (blk == 1) ? Wk : (blk == 2) ? Wv : Wr;
        split2(W[i * HID_ + h], g_W4h[t], g_W4l[t]);
    }
    if (t < 512) {
        int blk = t >> 7, h = t & 127;
        const float* sb = (blk == 0) ? bq : (blk == 1) ? bk : (blk == 2) ? bv : br;
        g_B4[t] = sb[h];
    }
    if (t < 512 * HID_) {
        int o = t >> 7, d = t & 127;
        float w2 = Wc[(HID_ + d) * OUT_ + (o & 255)];
        float v  = (o < OUT_) ? w2 : (Wc[d * OUT_ + (o - OUT_)] - w2);
        split2(v, g_WMh[t], g_WMl[t]);
    }
}

// ---------------- shared MMA building blocks ----------------
#define BK      64
#define LDS_    72
#define TILEB_  (128 * LDS_ * 2)
#define TPITCH  132                      // transpose staging pitch (floats, 16B rows)
#define TILEA_  (128 * LDS_ * 2)
#define STAGE_  (2 * TILEA_ + 2 * TILEB_)   // 73728

template <int MI, int NJ>
__device__ __forceinline__ void compute_chunk(
    uint32_t uAh, uint32_t uAl, uint32_t uBh, uint32_t uBl,
    float (&acc)[MI][NJ][4], int lane, int arow0, int brow0) {
    const int arow = arow0 + (lane & 15);
    const int akof = ((lane >> 4) << 3);
    const int brow = brow0 + (lane & 7);
    const int bkof = ((lane >> 3) & 1) << 3;
#pragma unroll
    for (int ks = 0; ks < BK / 16; ks++) {
        const int kk = ks * 16;
        uint32_t aH[MI][4], aL[MI][4], bH[NJ][2], bL[NJ][2];
#pragma unroll
        for (int i = 0; i < MI; i++)
            ldsm4(aH[i], uAh + (uint32_t)(((arow + i * 16) * LDS_ + kk + akof) * 2));
#pragma unroll
        for (int j = 0; j < NJ; j++)
            ldsm2(bH[j], uBh + (uint32_t)(((brow + j * 8) * LDS_ + kk + bkof) * 2));
#pragma unroll
        for (int i = 0; i < MI; i++)
#pragma unroll
            for (int j = 0; j < NJ; j++) mma16816(acc[i][j], aH[i], bH[j]);
#pragma unroll
        for (int i = 0; i < MI; i++)
            ldsm4(aL[i], uAl + (uint32_t)(((arow + i * 16) * LDS_ + kk + akof) * 2));
#pragma unroll
        for (int i = 0; i < MI; i++)
#pragma unroll
            for (int j = 0; j < NJ; j++) mma16816(acc[i][j], aL[i], bH[j]);
#pragma unroll
        for (int j = 0; j < NJ; j++)
            ldsm2(bL[j], uBl + (uint32_t)(((brow + j * 8) * LDS_ + kk + bkof) * 2));
#pragma unroll
        for (int i = 0; i < MI; i++)
#pragma unroll
            for (int j = 0; j < NJ; j++) mma16816(acc[i][j], aH[i], bL[j]);
    }
}

__device__ __forceinline__ void load_tiles_chunk(
    uint32_t ub, const bf16* Ah, const bf16* Al, const bf16* Bh, const bf16* Bl,
    int lda, int ldb, int k0, int tid) {
#pragma unroll
    for (int i = 0; i < 2; i++) {
        int idx = tid + i * 512;
        int r = idx >> 3, c8 = (idx & 7) << 3;
        uint32_t sdst = (uint32_t)((r * LDS_ + c8) * 2);
        cpa16(ub + sdst,          Ah + (size_t)r * lda + k0 + c8);
        cpa16(ub + TILEA_ + sdst, Al + (size_t)r * lda + k0 + c8);
    }
#pragma unroll
    for (int i = 0; i < 2; i++) {
        int idx = tid + i * 512;
        int r = idx >> 3, c8 = (idx & 7) << 3;
        uint32_t sdst = (uint32_t)((r * LDS_ + c8) * 2);
        cpa16(ub + 2 * TILEA_ + sdst,          Bh + (size_t)r * ldb + k0 + c8);
        cpa16(ub + 2 * TILEA_ + TILEB_ + sdst, Bl + (size_t)r * ldb + k0 + c8);
    }
    cpa_commit();
}

// ---------------- QKVR: X @ [Wq|Wk|Wv|Wr] + bias ----------------
__global__ void __launch_bounds__(512, 1) qkvr_kernel() {
    constexpr int nc = IN_ / BK;   // 4
    constexpr int NST = 3;
    extern __shared__ char smem[];
    const int tid = threadIdx.x, lane = tid & 31, w = tid >> 5;
    const int wm = w % 4, wn = w / 4;
    const int nT = blockIdx.x, mT = blockIdx.y;

    const bf16* Ah = g_Xh + (size_t)mT * 128 * IN_;
    const bf16* Al = g_Xl + (size_t)mT * 128 * IN_;
    const bf16* Bh = g_W4h + (size_t)nT * 128 * IN_;
    const bf16* Bl = g_W4l + (size_t)nT * 128 * IN_;

    const uint32_t ubase = s2u(smem);
    float acc[2][4][4] = {};

#pragma unroll
    for (int p = 0; p < NST - 1; p++)
        load_tiles_chunk(ubase + p * STAGE_, Ah, Al, Bh, Bl, IN_, IN_, p * BK, tid);
#pragma unroll
    for (int c = 0; c < nc; c++) {
        if (c + NST - 1 < nc) {
            load_tiles_chunk(ubase + ((c + NST - 1) % NST) * STAGE_, Ah, Al, Bh, Bl,
                             IN_, IN_, (c + NST - 1) * BK, tid);
            cpa_wait<NST - 1>();
        } else if (c + 2 < nc) cpa_wait<2>();
        else if (c + 1 < nc)   cpa_wait<1>();
        else                   cpa_wait<0>();
        __syncthreads();
        const uint32_t ub = ubase + (c % NST) * STAGE_;
        compute_chunk<2, 4>(ub, ub + TILEA_, ub + 2 * TILEA_, ub + 2 * TILEA_ + TILEB_,
                            acc, lane, wm * 32, wn * 32);
        __syncthreads();
    }

    const int r_base = wm * 32 + (lane >> 2);
    const int c_base = wn * 32 + ((lane & 3) << 1);

    if (nT == 2) {   // V -> transposed splits via smem
        float* Cs = (float*)smem;   // [128][129] scalar access
#pragma unroll
        for (int i = 0; i < 2; i++)
#pragma unroll
            for (int j = 0; j < 4; j++) {
                int r = r_base + i * 16, c = c_base + j * 8;
                Cs[r * 129 + c]           = acc[i][j][0] + g_B4[256 + c];
                Cs[r * 129 + c + 1]       = acc[i][j][1] + g_B4[256 + c + 1];
                Cs[(r + 8) * 129 + c]     = acc[i][j][2] + g_B4[256 + c];
                Cs[(r + 8) * 129 + c + 1] = acc[i][j][3] + g_B4[256 + c + 1];
            }
        __syncthreads();
        const int bb = mT >> 2, m0 = (mT & 3) * 128;
        const int d = tid >> 2, ms = (tid & 3) * 32;
        size_t base = ((size_t)bb * HID_ + d) * N_ + m0 + ms;
#pragma unroll 8
        for (int k = 0; k < 32; k++)
            split2(Cs[(ms + k) * 129 + d], g_VTh[base + k], g_VTl[base + k]);
        return;
    }

#pragma unroll
    for (int i = 0; i < 2; i++)
#pragma unroll
        for (int j = 0; j < 4; j++)
#pragma unroll
            for (int h = 0; h < 2; h++) {
                const int r = r_base + i * 16 + h * 8;
                const int c = c_base + j * 8;
                float v0 = acc[i][j][h * 2], v1 = acc[i][j][h * 2 + 1];
                size_t grow = (size_t)mT * 128 + r;
                if (nT == 0 || nT == 1) {
                    bf16* Dh = (nT == 0) ? g_Qh : g_Kh;
                    bf16* Dl = (nT == 0) ? g_Ql : g_Kl;
                    split2(v0 + g_B4[nT * 128 + c],     Dh[grow * HID_ + c],     Dl[grow * HID_ + c]);
                    split2(v1 + g_B4[nT * 128 + c + 1], Dh[grow * HID_ + c + 1], Dl[grow * HID_ + c + 1]);
                } else {
                    *(float2*)(g_R + grow * HID_ + c) =
                        make_float2(v0 + g_B4[384 + c], v1 + g_B4[384 + c + 1]);
                }
            }
}

// ---------------- GRAM: scores = 2 H H^T - ||h_m||^2 (upper-tri, staged transpose) --
__global__ void __launch_bounds__(512, 1) gram_kernel() {
    extern __shared__ char smem[];
    const int tid = threadIdx.x, lane = tid & 31, w = tid >> 5;
    const int wm = w % 4, wn = w / 4;
    const int b = blockIdx.z;
    int t = blockIdx.x;
    int mT = (t < 1) ? 0 : (t < 3) ? 1 : (t < 6) ? 2 : 3;
    const int tri[4] = {0, 1, 3, 6};
    int nT = t - tri[mT];

    size_t ar = ((size_t)b * N_ + mT * 128) * HID_;
    const bf16* Ah = g_Hh + ar; const bf16* Al = g_Hl + ar;
    size_t br_ = ((size_t)b * N_ + nT * 128) * HID_;
    const bf16* Bh = g_Hh + br_; const bf16* Bl = g_Hl + br_;

    const uint32_t ubase = s2u(smem);
    float acc[2][4][4] = {};

    load_tiles_chunk(ubase, Ah, Al, Bh, Bl, HID_, HID_, 0, tid);
    load_tiles_chunk(ubase + STAGE_, Ah, Al, Bh, Bl, HID_, HID_, BK, tid);
#pragma unroll
    for (int c = 0; c < 2; c++) {
        if (c == 0) cpa_wait<1>(); else cpa_wait<0>();
        __syncthreads();
        const uint32_t ub = ubase + c * STAGE_;
        compute_chunk<2, 4>(ub, ub + TILEA_, ub + 2 * TILEA_, ub + 2 * TILEA_ + TILEB_,
                            acc, lane, wm * 32, wn * 32);
        __syncthreads();
    }

    const int r_base = wm * 32 + (lane >> 2);
    const int c_base = wn * 32 + ((lane & 3) << 1);
    float* Ts = (float*)smem;

#pragma unroll
    for (int i = 0; i < 2; i++)
#pragma unroll
        for (int j = 0; j < 4; j++)
#pragma unroll
            for (int h = 0; h < 2; h++) {
                const int r = r_base + i * 16 + h * 8;
                const int c = c_base + j * 8;
                float v0 = acc[i][j][h * 2], v1 = acc[i][j][h * 2 + 1];
                size_t row = (size_t)b * N_ + mT * 128 + r;
                float s0 = 2.f * v0 - g_SQ[(size_t)b * N_ + nT * 128 + c];
                float s1 = 2.f * v1 - g_SQ[(size_t)b * N_ + nT * 128 + c + 1];
                *(float2*)(g_S + row * N_ + nT * 128 + c) = make_float2(s0, s1);
                if (mT != nT) {
                    float sqr = g_SQ[(size_t)b * N_ + mT * 128 + r];
                    Ts[c * TPITCH + r]       = 2.f * v0 - sqr;
                    Ts[(c + 1) * TPITCH + r] = 2.f * v1 - sqr;
                }
            }

    if (mT != nT) {
        __syncthreads();
        const int c = tid >> 2, ch = (tid & 3) * 32;
        size_t orow = ((size_t)b * N_ + nT * 128 + c) * N_ + mT * 128 + ch;
#pragma unroll
        for (int k = 0; k < 8; k++)
            *(float4*)(g_S + orow + k * 4) = *(const float4*)(Ts + c * TPITCH + ch + k * 4);
    }
}

// ---------------- ZG = H @ [Wc2 | Wc1-Wc2] ----------------
__global__ void __launch_bounds__(512, 1) zg_kernel() {
    extern __shared__ char smem[];
    const int tid = threadIdx.x, lane = tid & 31, w = tid >> 5;
    const int wm = w % 4, wn = w / 4;
    const int nT = blockIdx.x, mT = blockIdx.y;

    const bf16* Ah = g_Hh + (size_t)mT * 128 * HID_;
    const bf16* Al = g_Hl + (size_t)mT * 128 * HID_;
    const bf16* Bh = g_WMh + (size_t)nT * 128 * HID_;
    const bf16* Bl = g_WMl + (size_t)nT * 128 * HID_;

    const uint32_t ubase = s2u(smem);
    float acc[2][4][4] = {};

    load_tiles_chunk(ubase, Ah, Al, Bh, Bl, HID_, HID_, 0, tid);
    load_tiles_chunk(ubase + STAGE_, Ah, Al, Bh, Bl, HID_, HID_, BK, tid);
#pragma unroll
    for (int c = 0; c < 2; c++) {
        if (c == 0) cpa_wait<1>(); else cpa_wait<0>();
        __syncthreads();
        const uint32_t ub = ubase + c * STAGE_;
        compute_chunk<2, 4>(ub, ub + TILEA_, ub + 2 * TILEA_, ub + 2 * TILEA_ + TILEB_,
                            acc, lane, wm * 32, wn * 32);
        __syncthreads();
    }

    const int r_base = wm * 32 + (lane >> 2);
    const int c_base = wn * 32 + ((lane & 3) << 1);
#pragma unroll
    for (int i = 0; i < 2; i++)
#pragma unroll
        for (int j = 0; j < 4; j++)
#pragma unroll
            for (int h = 0; h < 2; h++) {
                const int r = r_base + i * 16 + h * 8;
                const int c = c_base + j * 8;
                size_t row = (size_t)mT * 128 + r;
                *(float2*)(g_ZG + row * 512 + nT * 128 + c) =
                    make_float2(acc[i][j][h * 2], acc[i][j][h * 2 + 1]);
            }
}

// ------- fused attention: S = QK^T/sqrt -> softmax -> H = P V + R (+||h||^2) ------
#define QLDS    136
#define Q_TILE  (64 * QLDS * 2)            // 17408
#define KT_TILE (128 * QLDS * 2)           // 34816
#define K_STAGE (2 * KT_TILE)              // 69632
#define ATT_K0  (2 * Q_TILE)               // 34816
#define PLDS    520
#define P_TILE  (64 * PLDS * 2)            // 66560
#define V_OFF   (2 * P_TILE)               // 133120
#define V_HALF  (128 * 72 * 2)             // 18432
#define V_STAGE (2 * V_HALF)               // 36864
#define RED_OFF (V_OFF + 2 * V_STAGE)      // 206848
#define SQ_OFF  (RED_OFF + 2 * 2304)       // 211456
#define SM_ATTN (SQ_OFF + 2048)            // 213504

__global__ void __launch_bounds__(512, 1) attn_kernel() {
    extern __shared__ char smem[];
    const int tid = threadIdx.x, lane = tid & 31, w = tid >> 5;
    const int wm = w & 1, wn = w >> 1;       // 2 M-groups x 8 N-groups
    const int mT = blockIdx.x, b = blockIdx.y;
    const size_t q0 = (size_t)b * N_ + mT * 64;
    const uint32_t ubase = s2u(smem);
    const uint32_t uQh = ubase, uQl = ubase + Q_TILE;

#pragma unroll
    for (int it = 0; it < 2; it++) {
        int idx = tid + it * 512;
        int r = idx >> 4, c8 = (idx & 15) << 3;
        uint32_t dst = (uint32_t)((r * QLDS + c8) * 2);
        cpa16(uQh + dst, g_Qh + (q0 + r) * HID_ + c8);
        cpa16(uQl + dst, g_Ql + (q0 + r) * HID_ + c8);
    }
    cpa_commit();

    const size_t kr0 = (size_t)b * N_;
    auto loadK = [&](int s, int buf) {
        const uint32_t ub = ubase + ATT_K0 + buf * K_STAGE;
        const bf16* Kh = g_Kh + (kr0 + s * 128) * HID_;
        const bf16* Kl = g_Kl + (kr0 + s * 128) * HID_;
#pragma unroll
        for (int it = 0; it < 4; it++) {
            int idx = tid + it * 512;
            int r = idx >> 4, c8 = (idx & 15) << 3;
            uint32_t dst = (uint32_t)((r * QLDS + c8) * 2);
            cpa16(ub + dst,           Kh + (size_t)r * HID_ + c8);
            cpa16(ub + KT_TILE + dst, Kl + (size_t)r * HID_ + c8);
        }
        cpa_commit();
    };

    float acc[2][8][4] = {};
    loadK(0, 0);
    for (int s = 0; s < 4; s++) {
        if (s + 1 < 4) { loadK(s + 1, (s + 1) & 1); cpa_wait<1>(); }
        else           cpa_wait<0>();
        __syncthreads();
        const uint32_t uKh = ubase + ATT_K0 + (s & 1) * K_STAGE;
        const uint32_t uKl = uKh + KT_TILE;
        const int arow = wm * 32 + (lane & 15);
        const int akof = (lane >> 4) << 3;
        const int brow = wn * 16 + (lane & 7);
        const int bkof = ((lane >> 3) & 1) << 3;
#pragma unroll
        for (int ks = 0; ks < 8; ks++) {
            const int kk = ks * 16;
            uint32_t aH[2][4], aL[2][4], bH[2][2], bL[2][2];
#pragma unroll
            for (int i = 0; i < 2; i++) {
                ldsm4(aH[i], uQh + (uint32_t)(((arow + i * 16) * QLDS + kk + akof) * 2));
                ldsm4(aL[i], uQl + (uint32_t)(((arow + i * 16) * QLDS + kk + akof) * 2));
            }
#pragma unroll
            for (int j = 0; j < 2; j++) {
                uint32_t ba = (uint32_t)(((brow + j * 8) * QLDS + kk + bkof) * 2);
                ldsm2(bH[j], uKh + ba);
                ldsm2(bL[j], uKl + ba);
            }
#pragma unroll
            for (int i = 0; i < 2; i++)
#pragma unroll
                for (int j = 0; j < 2; j++) {
                    mma16816(acc[i][s * 2 + j], aH[i], bH[j]);
                    mma16816(acc[i][s * 2 + j], aL[i], bH[j]);
                    mma16816(acc[i][s * 2 + j], aH[i], bL[j]);
                }
        }
        __syncthreads();
    }

    auto loadV = [&](int c, int buf) {
        const uint32_t ub = ubase + V_OFF + buf * V_STAGE;
        const bf16* Vh = g_VTh + (size_t)b * HID_ * N_ + c * 64;
        const bf16* Vl = g_VTl + (size_t)b * HID_ * N_ + c * 64;
#pragma unroll
        for (int it = 0; it < 2; it++) {
            int idx = tid + it * 512;
            int r = idx >> 3, c8 = (idx & 7) << 3;
            uint32_t dst = (uint32_t)((r * 72 + c8) * 2);
            cpa16(ub + dst,          Vh + (size_t)r * N_ + c8);
            cpa16(ub + V_HALF + dst, Vl + (size_t)r * N_ + c8);
        }
        cpa_commit();
    };
    loadV(0, 0);

    // ---- softmax over 512 keys (cross-warp via smem) ----
    float* red  = (float*)(smem + RED_OFF);
    float* red2 = (float*)(smem + RED_OFF + 2304);
    const int rq = lane >> 2;
    const float scale = 0.08838834764831843f;
#pragma unroll
    for (int i = 0; i < 2; i++)
#pragma unroll
        for (int nj = 0; nj < 8; nj++)
#pragma unroll
            for (int q = 0; q < 4; q++) acc[i][nj][q] *= scale;

#pragma unroll
    for (int i = 0; i < 2; i++)
#pragma unroll
        for (int h = 0; h < 2; h++) {
            float m = -INFINITY;
#pragma unroll
            for (int nj = 0; nj < 8; nj++)
                m = fmaxf(m, fmaxf(acc[i][nj][h * 2], acc[i][nj][h * 2 + 1]));
            m = fmaxf(m, __shfl_xor_sync(0xffffffffu, m, 1));
            m = fmaxf(m, __shfl_xor_sync(0xffffffffu, m, 2));
            if ((lane & 3) == 0) red[(wm * 32 + i * 16 + h * 8 + rq) * 9 + wn] = m;
        }
    __syncthreads();
    float rm[2][2], ri[2][2];
#pragma unroll
    for (int i = 0; i < 2; i++)
#pragma unroll
        for (int h = 0; h < 2; h++) {
            int row = wm * 32 + i * 16 + h * 8 + rq;
            float m = red[row * 9];
#pragma unroll
            for (int g = 1; g < 8; g++) m = fmaxf(m, red[row * 9 + g]);
            rm[i][h] = m;
        }
#pragma unroll
    for (int i = 0; i < 2; i++)
#pragma unroll
        for (int h = 0; h < 2; h++) {
            float sum = 0.f;
#pragma unroll
            for (int nj = 0; nj < 8; nj++) {
                float e0 = __expf(acc[i][nj][h * 2]     - rm[i][h]);
                float e1 = __expf(acc[i][nj][h * 2 + 1] - rm[i][h]);
                acc[i][nj][h * 2] = e0; acc[i][nj][h * 2 + 1] = e1;
                sum += e0 + e1;
            }
            sum += __shfl_xor_sync(0xffffffffu, sum, 1);
            sum += __shfl_xor_sync(0xffffffffu, sum, 2);
            if ((lane & 3) == 0) red2[(wm * 32 + i * 16 + h * 8 + rq) * 9 + wn] = sum;
        }
    __syncthreads();
#pragma unroll
    for (int i = 0; i < 2; i++)
#pragma unroll
        for (int h = 0; h < 2; h++) {
            int row = wm * 32 + i * 16 + h * 8 + rq;
            float sum = 0.f;
#pragma unroll
            for (int g = 0; g < 8; g++) sum += red2[row * 9 + g];
            ri[i][h] = 1.f / sum;
        }

    // ---- stage P (bf16 h/l) in smem at offset 0 (Q/K regions are dead) ----
    char* pPh = smem;
    char* pPl = smem + P_TILE;
#pragma unroll
    for (int i = 0; i < 2; i++)
#pragma unroll
        for (int nj = 0; nj < 8; nj++)
#pragma unroll
            for (int h = 0; h < 2; h++) {
                int row = wm * 32 + i * 16 + h * 8 + rq;
                int key = (nj >> 1) * 128 + wn * 16 + (nj & 1) * 8 + ((lane & 3) << 1);
                float p0 = acc[i][nj][h * 2] * ri[i][h];
                float p1 = acc[i][nj][h * 2 + 1] * ri[i][h];
                bf16 h0, l0, h1, l1;
                split2(p0, h0, l0); split2(p1, h1, l1);
                __nv_bfloat162 ph; ph.x = h0; ph.y = h1;
                __nv_bfloat162 pl; pl.x = l0; pl.y = l1;
                *(__nv_bfloat162*)(pPh + (row * PLDS + key) * 2) = ph;
                *(__nv_bfloat162*)(pPl + (row * PLDS + key) * 2) = pl;
            }

    // ---- phase C: H = P V (+R), 8 chunks of 64 keys ----
    float acc2[2][2][4] = {};
    const uint32_t uPh = ubase, uPl = ubase + P_TILE;
    for (int c = 0; c < 8; c++) {
        if (c + 1 < 8) { loadV(c + 1, (c + 1) & 1); cpa_wait<1>(); }
        else           cpa_wait<0>();
        __syncthreads();   // also publishes P staging on c==0
        const uint32_t uVh = ubase + V_OFF + (c & 1) * V_STAGE;
        const uint32_t uVl = uVh + V_HALF;
        const int arow = wm * 32 + (lane & 15);
        const int akof = (lane >> 4) << 3;
        const int brow = wn * 16 + (lane & 7);
        const int bkof = ((lane >> 3) & 1) << 3;
#pragma unroll
        for (int ks = 0; ks < 4; ks++) {
            const int pk = c * 64 + ks * 16 + akof;
            const int vk = ks * 16 + bkof;
            uint32_t aH[2][4], aL[2][4], bH[2][2], bL[2][2];
#pragma unroll
            for (int i = 0; i < 2; i++) {
                ldsm4(aH[i], uPh + (uint32_t)(((arow + i * 16) * PLDS + pk) * 2));
                ldsm4(aL[i], uPl + (uint32_t)(((arow + i * 16) * PLDS + pk) * 2));
            }
#pragma unroll
            for (int j = 0; j < 2; j++) {
                uint32_t ba = (uint32_t)(((brow + j * 8) * 72 + vk) * 2);
                ldsm2(bH[j], uVh + ba);
                ldsm2(bL[j], uVl + ba);
            }
#pragma unroll
            for (int i = 0; i < 2; i++)
#pragma unroll
                for (int j = 0; j < 2; j++) {
                    mma16816(acc2[i][j], aH[i], bH[j]);
                    mma16816(acc2[i][j], aL[i], bH[j]);
                    mma16816(acc2[i][j], aH[i], bL[j]);
                }
        }
        __syncthreads();
    }

    // ---- epilogue: H = acc2 + R ; splits ; ||h||^2 ----
    float rsq[2][2] = {{0.f, 0.f}, {0.f, 0.f}};
#pragma unroll
    for (int i = 0; i < 2; i++)
#pragma unroll
        for (int j = 0; j < 2; j++)
#pragma unroll
            for (int h = 0; h < 2; h++) {
                int row = wm * 32 + i * 16 + h * 8 + rq;
                int col = wn * 16 + j * 8 + ((lane & 3) << 1);
                size_t grow = q0 + row;
                float v0 = acc2[i][j][h * 2]     + g_R[grow * HID_ + col];
                float v1 = acc2[i][j][h * 2 + 1] + g_R[grow * HID_ + col + 1];
                split2(v0, g_Hh[grow * HID_ + col],     g_Hl[grow * HID_ + col]);
                split2(v1, g_Hh[grow * HID_ + col + 1], g_Hl[grow * HID_ + col + 1]);
                rsq[i][h] = fmaf(v0, v0, fmaf(v1, v1, rsq[i][h]));
            }
    float* sq_s = (float*)(smem + SQ_OFF);
#pragma unroll
    for (int i = 0; i < 2; i++)
#pragma unroll
        for (int h = 0; h < 2; h++) {
            float v = rsq[i][h];
            v += __shfl_xor_sync(0xffffffffu, v, 1);
            v += __shfl_xor_sync(0xffffffffu, v, 2);
            if ((lane & 3) == 0)
                sq_s[wn * 64 + wm * 32 + i * 16 + h * 8 + rq] = v;
        }
    __syncthreads();
    if (tid < 64) {
        float t = 0.f;
#pragma unroll
        for (int g = 0; g < 8; g++) t += sq_s[g * 64 + tid];
        g_SQ[q0 + tid] = t;
    }
}

// ---------------- top-16 by score (warp per row) ----------------
__global__ __launch_bounds__(256)
void topk_kernel() {
    const int tid = threadIdx.x, lane = tid & 31, w = tid >> 5;
    const int n = blockIdx.x * 8 + w;
    const float* srow = g_S + (size_t)n * N_;
    float cand[16];
#pragma unroll
    for (int s = 0; s < 16; s++) cand[s] = srow[s * 32 + lane];
    const int base = n & ~511;
    unsigned used = 0;
    for (int sel = 0; sel < K_; sel++) {
        float best = -INFINITY;
        int bslot = -1;
#pragma unroll
        for (int s = 0; s < 16; s++)
            if (!((used >> s) & 1u) && cand[s] > best) { best = cand[s]; bslot = s; }
        int   bm = (bslot >= 0) ? ((bslot << 5) | lane) : 0x3fffffff;
        float bv = best;
#pragma unroll
        for (int off = 16; off; off >>= 1) {
            float ov = __shfl_xor_sync(0xffffffffu, bv, off);
            int   om = __shfl_xor_sync(0xffffffffu, bm, off);
            if (ov > bv || (ov == bv && om < bm)) { bv = ov; bm = om; }
        }
        if ((bm & 31) == lane && (bm >> 5) < 16) used |= 1u << (bm >> 5);
        if (lane == 0) g_IDX[(size_t)n * K_ + sel] = base + bm;
    }
}

// ---------------- gather-max + layernorm + selu ----------------
__global__ __launch_bounds__(256)
void final_kernel(const float* __restrict__ bc, const float* __restrict__ lnsc,
                  const float* __restrict__ lnbi, float* __restrict__ out) {
    const int n = blockIdx.x;
    const int o = threadIdx.x;
    const int lane = o & 31, w = o >> 5;
    __shared__ int   sidx[K_];
    __shared__ float red[8];
    __shared__ float sstat;
    if (o < K_) sidx[o] = g_IDX[n * K_ + o];
    __syncthreads();
    float v = -INFINITY;
#pragma unroll
    for (int k = 0; k < K_; k++) v = fmaxf(v, g_ZG[(size_t)sidx[k] * 512 + o]);
    float y = v + g_ZG[(size_t)n * 512 + OUT_ + o] + bc[o];
    float s = y;
#pragma unroll
    for (int off = 16; off; off >>= 1) s += __shfl_xor_sync(0xffffffffu, s, off);
    if (lane == 0) red[w] = s;
    __syncthreads();
    if (o == 0) {
        float t = 0.f;
        for (int i = 0; i < 8; i++) t += red[i];
        sstat = t * (1.f / OUT_);
    }
    __syncthreads();
    const float mu = sstat;
    float d = y - mu;
    s = d * d;
#pragma unroll
    for (int off = 16; off; off >>= 1) s += __shfl_xor_sync(0xffffffffu, s, off);
    if (lane == 0) red[w] = s;
    __syncthreads();
    if (o == 0) {
        float t = 0.f;
        for (int i = 0; i < 8; i++) t += red[i];
        sstat = t * (1.f / OUT_);
    }
    __syncthreads();
    const float var = sstat;
    float nv = d * rsqrtf(var + 1e-5f) * lnsc[o] + lnbi[o];
    float r = nv > 0.f ? 1.0507009873554805f * nv
                       : 1.7580993408473766f * expm1f(nv);
    out[(size_t)n * OUT_ + o] = r;
}

// ---------------- launcher (fork/join: {GRAM->topk} || {ZG}) ----------------
extern "C" void kernel_launch(void* const* d_in, const int* in_sizes, int n_in,
                              void* d_out, int out_size) {
    const float* obj = (const float*)d_in[0];
    const float* Wq  = (const float*)d_in[2];
    const float* bq  = (const float*)d_in[3];
    const float* Wk  = (const float*)d_in[4];
    const float* bk  = (const float*)d_in[5];
    const float* Wv  = (const float*)d_in[6];
    const float* bv  = (const float*)d_in[7];
    const float* Wr  = (const float*)d_in[8];
    const float* br  = (const float*)d_in[9];
    const float* Wc  = (const float*)d_in[10];
    const float* bc  = (const float*)d_in[11];
    const float* lns = (const float*)d_in[12];
    const float* lnb = (const float*)d_in[13];
    float* out = (float*)d_out;

    constexpr int SM0  = 3 * STAGE_ + 2048;
    constexpr int SM34 = 2 * STAGE_ + 2048;

    static cudaStream_t sB = nullptr;
    static cudaEvent_t evFork = nullptr, evB = nullptr;
    if (!sB) {
        cudaStreamCreateWithFlags(&sB, cudaStreamNonBlocking);
        cudaEventCreateWithFlags(&evFork, cudaEventDisableTiming);
        cudaEventCreateWithFlags(&evB, cudaEventDisableTiming);
        cudaFuncSetAttribute(qkvr_kernel, cudaFuncAttributeMaxDynamicSharedMemorySize, SM0);
        cudaFuncSetAttribute(gram_kernel, cudaFuncAttributeMaxDynamicSharedMemorySize, SM34);
        cudaFuncSetAttribute(zg_kernel,   cudaFuncAttributeMaxDynamicSharedMemorySize, SM34);
        cudaFuncSetAttribute(attn_kernel, cudaFuncAttributeMaxDynamicSharedMemorySize, SM_ATTN);
    }

    // 1) convert inputs / pack weights (bf16 hi/lo splits), vectorized
    convert_kernel<<<ROWS_ * IN_ / 1024, 256>>>(obj, Wq, bq, Wk, bk, Wv, bv, Wr, br, Wc);
    // 2) QKVR
    qkvr_kernel<<<dim3(4, 64, 1), 512, SM0>>>();
    // 3) fused attention
    attn_kernel<<<dim3(8, B_), 512, SM_ATTN>>>();
    // fork: side stream runs ZG while main runs GRAM -> topk
    cudaEventRecord(evFork, 0);
    cudaStreamWaitEvent(sB, evFork, 0);
    zg_kernel<<<dim3(4, 64, 1), 512, SM34, sB>>>();
    cudaEventRecord(evB, sB);
    gram_kernel<<<dim3(10, 1, B_), 512, SM34>>>();
    topk_kernel<<<ROWS_ / 8, 256>>>();
    cudaStreamWaitEvent(0, evB, 0);
    // join: final needs both ZG and topk
    final_kernel<<<ROWS_, 256>>>(bc, lns, lnb, out);
}